// round 3
// baseline (speedup 1.0000x reference)
#include <cuda_runtime.h>
#include <cuda_bf16.h>

#define B_    2
#define T_    1024
#define H_    8
#define BHN   16
#define NLEV_ 11
#define BM    64
#define D_    64
#define LDA   68          // padded float stride: 16B-aligned rows for float4 LDS
#define THREADS 256

// cumsum scratch: cumg[b*H+h][t]
__device__ float d_cumg[BHN * T_];

// Inclusive scan of g over time per (b,h). One block per (b,h), 1024 threads.
__global__ void __launch_bounds__(1024) scan_kernel(const float* __restrict__ g) {
    __shared__ float s[T_];
    int bh = blockIdx.x;
    int b = bh >> 3, h = bh & 7;
    int t = threadIdx.x;
    s[t] = g[(b * T_ + t) * H_ + h];
    __syncthreads();
    #pragma unroll
    for (int off = 1; off < T_; off <<= 1) {
        float add = (t >= off) ? s[t - off] : 0.0f;
        __syncthreads();
        s[t] += add;
        __syncthreads();
    }
    d_cumg[bh * T_ + t] = s[t];
}

// grid = 128 blocks = 16 (b,h) x 8 balanced row-tile pairs {p, 15-p}.
// W[i,j] = [j<=i] * exp(cumg_i)*L[lev(i,j), i] * exp(-cumg_j),
//   lev(i,j) = 32-clz(i^j) (0 on diagonal); exp(cumg_i) folded into Lrow.
// Software pipeline: K/V of tile ct+1 prefetched into registers during GEMM1,
// written to smem after the mid barrier (Ks/Ec single-buffered, Vs double).
__global__ void __launch_bounds__(THREADS) hattn_kernel(
    const float* __restrict__ q, const float* __restrict__ k,
    const float* __restrict__ v, const float* __restrict__ Lsc,
    float* __restrict__ out)
{
    extern __shared__ float sm[];
    float* Qs   = sm;                   // [D_][LDA]   Qs[d][i]  (transposed)
    float* Ks   = Qs + D_ * LDA;        // [D_][LDA]   Ks[d][j]  (transposed)
    float* Ss   = Ks + D_ * LDA;        // [BM][LDA]   Ss[j][i]  (S transposed)
    float* Vs   = Ss + BM * LDA;        // [2][BM][D_] double-buffered
    float* Lrow = Vs + 2 * BM * D_;     // [NLEV_][BM] pre-scaled by exp(cumg_i)
    float* Ec   = Lrow + NLEV_ * BM;    // [BM]        exp(-cumg_j) of cols

    const int blk  = blockIdx.x;
    const int bh   = blk & 15;
    const int pair = blk >> 4;          // 0..7
    const int b = bh >> 3, h = bh & 7;
    const int tid = threadIdx.x;
    const int tx = tid & 15, ty = tid >> 4;

    // load-mapping lanes: Q/K scalar (d fastest -> coalesced), V float4
    const int dK  = tid & 63;           // fixed d for this thread
    const int cK0 = tid >> 6;           // row/col base, +4 per step
    const int d4V = tid & 15;           // float4 index within row
    const int cV0 = tid >> 4;           // row base, +16 per step

    const float* cg = d_cumg + bh * T_;

    for (int rr = 0; rr < 2; rr++) {
        const int r = rr ? (15 - pair) : pair;
        const int row0 = r * BM;

        // Q tile (transposed), level scales * exp(cumg_i), K/V tile 0, Ec 0.
        #pragma unroll
        for (int s = 0; s < 16; s++) {
            int i = cK0 + 4 * s;
            Qs[dK * LDA + i] = q[((b * T_ + row0 + i) * H_ + h) * D_ + dK];
        }
        for (int e = tid; e < NLEV_ * BM; e += THREADS) {
            int lev = e >> 6, i = e & 63;
            Lrow[e] = Lsc[(bh * NLEV_ + lev) * T_ + row0 + i]
                      * __expf(cg[row0 + i]);
        }
        #pragma unroll
        for (int s = 0; s < 16; s++) {
            int c = cK0 + 4 * s;
            Ks[dK * LDA + c] = k[((b * T_ + c) * H_ + h) * D_ + dK];
        }
        #pragma unroll
        for (int s = 0; s < 4; s++) {
            int c = cV0 + 16 * s;
            *(float4*)&Vs[c * D_ + 4 * d4V] =
                *(const float4*)&v[((b * T_ + c) * H_ + h) * D_ + 4 * d4V];
        }
        if (tid < BM) Ec[tid] = __expf(-cg[tid]);

        float accO[4][4];
        #pragma unroll
        for (int a = 0; a < 4; a++)
            #pragma unroll
            for (int p = 0; p < 4; p++) accO[a][p] = 0.0f;

        __syncthreads();

        int cur = 0;
        for (int ct = 0; ct <= r; ct++) {
            // ---- prefetch tile ct+1 into registers (latency hides under GEMM1)
            float  kreg[16];
            float4 vreg[4];
            float  cgn = 0.0f;
            const bool pf = (ct < r);
            const int col0n = (ct + 1) * BM;
            if (pf) {
                #pragma unroll
                for (int s = 0; s < 16; s++) {
                    int c = cK0 + 4 * s;
                    kreg[s] = k[((b * T_ + col0n + c) * H_ + h) * D_ + dK];
                }
                #pragma unroll
                for (int s = 0; s < 4; s++) {
                    int c = cV0 + 16 * s;
                    vreg[s] = *(const float4*)
                        &v[((b * T_ + col0n + c) * H_ + h) * D_ + 4 * d4V];
                }
                if (tid < BM) cgn = cg[col0n + tid];
            }

            // ---- GEMM1: S = Q K^T (4x4 register tile)
            float accS[4][4];
            #pragma unroll
            for (int a = 0; a < 4; a++)
                #pragma unroll
                for (int bb = 0; bb < 4; bb++) accS[a][bb] = 0.0f;

            #pragma unroll 16
            for (int d = 0; d < D_; d++) {
                float4 qf = *(const float4*)&Qs[d * LDA + 4 * ty];
                float4 kf = *(const float4*)&Ks[d * LDA + 4 * tx];
                float qa[4] = {qf.x, qf.y, qf.z, qf.w};
                float kb[4] = {kf.x, kf.y, kf.z, kf.w};
                #pragma unroll
                for (int a = 0; a < 4; a++)
                    #pragma unroll
                    for (int bb = 0; bb < 4; bb++)
                        accS[a][bb] += qa[a] * kb[bb];
            }

            // ---- weight + store S transposed
            const int col0 = ct * BM;
            #pragma unroll
            for (int bb = 0; bb < 4; bb++) {
                const int jl = 4 * tx + bb;
                const int jg = col0 + jl;
                const float ecj = Ec[jl];
                float sv[4];
                #pragma unroll
                for (int a = 0; a < 4; a++) {
                    const int il = 4 * ty + a;
                    const int ig = row0 + il;
                    float w = 0.0f;
                    if (jg <= ig) {
                        unsigned x = (unsigned)(ig ^ jg);
                        int lev = x ? (32 - __clz(x)) : 0;
                        w = Lrow[lev * BM + il] * ecj;
                    }
                    sv[a] = accS[a][bb] * w;
                }
                *(float4*)&Ss[jl * LDA + 4 * ty] =
                    make_float4(sv[0], sv[1], sv[2], sv[3]);
            }
            __syncthreads();   // Ss visible; Ks/Ec readers done

            // ---- write next tiles (overlaps GEMM2 across warps)
            if (pf) {
                #pragma unroll
                for (int s = 0; s < 16; s++)
                    Ks[dK * LDA + cK0 + 4 * s] = kreg[s];
                float* Vn = Vs + (cur ^ 1) * BM * D_;
                #pragma unroll
                for (int s = 0; s < 4; s++)
                    *(float4*)&Vn[(cV0 + 16 * s) * D_ + 4 * d4V] = vreg[s];
                if (tid < BM) Ec[tid] = __expf(-cgn);
            }

            // ---- GEMM2: O += S V
            const float* Vc = Vs + cur * BM * D_;
            #pragma unroll 16
            for (int j = 0; j < BM; j++) {
                float4 sf = *(const float4*)&Ss[j * LDA + 4 * ty];
                float4 vf = *(const float4*)&Vc[j * D_ + 4 * tx];
                float sa[4] = {sf.x, sf.y, sf.z, sf.w};
                float vp[4] = {vf.x, vf.y, vf.z, vf.w};
                #pragma unroll
                for (int a = 0; a < 4; a++)
                    #pragma unroll
                    for (int p = 0; p < 4; p++)
                        accO[a][p] += sa[a] * vp[p];
            }
            __syncthreads();   // Vs[cur]/Ss readers done
            cur ^= 1;
        }

        // ---- store O tile: out[b, row0+i, h, p]
        #pragma unroll
        for (int a = 0; a < 4; a++) {
            const int i = row0 + 4 * ty + a;
            *(float4*)&out[((b * T_ + i) * H_ + h) * D_ + 4 * tx] =
                make_float4(accO[a][0], accO[a][1], accO[a][2], accO[a][3]);
        }
        // Next row tile rewrites smem only after the loop's final barrier.
    }
}

extern "C" void kernel_launch(void* const* d_in, const int* in_sizes, int n_in,
                              void* d_out, int out_size) {
    const float* q   = (const float*)d_in[0];
    const float* k   = (const float*)d_in[1];
    const float* v   = (const float*)d_in[2];
    const float* g   = (const float*)d_in[3];
    const float* Lsc = (const float*)d_in[4];
    float* out = (float*)d_out;

    const int smem_bytes =
        (2 * D_ * LDA + BM * LDA + 2 * BM * D_ + NLEV_ * BM + BM)
        * (int)sizeof(float);                                     // 88064
    cudaFuncSetAttribute(hattn_kernel,
                         cudaFuncAttributeMaxDynamicSharedMemorySize, smem_bytes);

    scan_kernel<<<BHN, T_>>>(g);
    hattn_kernel<<<128, THREADS, smem_bytes>>>(q, k, v, Lsc, out);
}

// round 12
// speedup vs baseline: 1.7032x; 1.7032x over previous
#include <cuda_runtime.h>
#include <cuda_bf16.h>
#include <cstdint>

#define B_    2
#define T_    1024
#define H_    8
#define BHN   16
#define NLEV_ 11
#define BM    64
#define BN    64
#define D_    64
#define THREADS 256

// smem byte offsets; all tiles have 128B rows (64 bf16), SW128 swizzle
#define QHI_OFF   0
#define QLO_OFF   8192
#define KHI_OFF   16384
#define KLO_OFF   24576
#define VT_OFF    32768     // [buf][split] 8192 each -> +buf*16384 +split*8192
#define SHI_OFF   65536
#define SLO_OFF   73728
#define LROW_OFF  81920     // float[11][64]
#define EC_OFF    84736     // float[2][64]
#define SMEM_TOTAL 85504

static __device__ float d_cumg[BHN * T_];

__device__ __forceinline__ uint32_t smem_u32(const void* p) {
    uint32_t a;
    asm("{ .reg .u64 t; cvta.to.shared.u64 t, %1; cvt.u32.u64 %0, t; }"
        : "=r"(a) : "l"(p));
    return a;
}
__device__ __forceinline__ uint32_t swz(uint32_t o) { return o ^ ((o >> 3) & 0x70); }

__device__ __forceinline__ void ldsm4(uint32_t& r0, uint32_t& r1, uint32_t& r2,
                                      uint32_t& r3, uint32_t a) {
    asm volatile("ldmatrix.sync.aligned.m8n8.x4.shared.b16 {%0,%1,%2,%3}, [%4];"
                 : "=r"(r0), "=r"(r1), "=r"(r2), "=r"(r3) : "r"(a));
}
__device__ __forceinline__ void mma16816(float* c, uint32_t a0, uint32_t a1,
                                         uint32_t a2, uint32_t a3,
                                         uint32_t b0, uint32_t b1) {
    asm volatile(
        "mma.sync.aligned.m16n8k16.row.col.f32.bf16.bf16.f32 "
        "{%0,%1,%2,%3}, {%4,%5,%6,%7}, {%8,%9}, {%0,%1,%2,%3};"
        : "+f"(c[0]), "+f"(c[1]), "+f"(c[2]), "+f"(c[3])
        : "r"(a0), "r"(a1), "r"(a2), "r"(a3), "r"(b0), "r"(b1));
}
__device__ __forceinline__ void sts64(uint32_t a, uint32_t r0, uint32_t r1) {
    asm volatile("st.shared.v2.b32 [%0], {%1,%2};" :: "r"(a), "r"(r0), "r"(r1) : "memory");
}
__device__ __forceinline__ void sts32(uint32_t a, uint32_t r0) {
    asm volatile("st.shared.b32 [%0], %1;" :: "r"(a), "r"(r0) : "memory");
}
// split (x0,x1) -> packed bf16x2 hi and lo residual
__device__ __forceinline__ void split2(float x0, float x1, uint32_t& hi, uint32_t& lo) {
    __nv_bfloat16 h0 = __float2bfloat16(x0), h1 = __float2bfloat16(x1);
    hi = ((uint32_t)__bfloat16_as_ushort(h1) << 16) | __bfloat16_as_ushort(h0);
    float l0 = x0 - __bfloat162float(h0);
    float l1 = x1 - __bfloat162float(h1);
    __nv_bfloat16 g0 = __float2bfloat16(l0), g1 = __float2bfloat16(l1);
    lo = ((uint32_t)__bfloat16_as_ushort(g1) << 16) | __bfloat16_as_ushort(g0);
}

__global__ void __launch_bounds__(1024) scan_kernel(const float* __restrict__ g) {
    __shared__ float s[T_];
    int bh = blockIdx.x;
    int b = bh >> 3, h = bh & 7;
    int t = threadIdx.x;
    s[t] = g[(b * T_ + t) * H_ + h];
    __syncthreads();
    #pragma unroll
    for (int off = 1; off < T_; off <<= 1) {
        float add = (t >= off) ? s[t - off] : 0.0f;
        __syncthreads();
        s[t] += add;
        __syncthreads();
    }
    d_cumg[bh * T_ + t] = s[t];
}

// grid = 128 = 16 (b,h) x 8 balanced row-tile pairs {p, 15-p} (64 rows each).
// W[i,j] = [j<=i]*exp(cumg_i)*L[lev(i,j),i]*exp(-cumg_j); lev = 32-clz(i^j).
// Both GEMMs run on HMMA (mma.sync m16n8k16 bf16) with error-compensated
// bf16 hi/lo splits (3 products each, lo*lo dropped).
__global__ void __launch_bounds__(THREADS) hattn_mma(
    const float* __restrict__ q, const float* __restrict__ k,
    const float* __restrict__ v, const float* __restrict__ Lsc,
    float* __restrict__ out)
{
    extern __shared__ char smem[];
    const uint32_t sb = smem_u32(smem);
    const int tid = threadIdx.x;
    const int lid = tid & 31, wid = tid >> 5;
    const int gid = lid >> 2, qcol = 2 * (lid & 3);
    const int wrow = (wid & 3) * 16, wcol = (wid >> 2) * 32;
    const int blk = blockIdx.x;
    const int bh = blk & 15, pair = blk >> 4;
    const int b = bh >> 3, h = bh & 7;

    float* Lrow = (float*)(smem + LROW_OFF);
    float* EcB  = (float*)(smem + EC_OFF);
    const float* cg = d_cumg + bh * T_;

    // load-mapping lanes
    const int d4 = tid & 15, rbv = tid >> 4;     // Q/K: float4 over d
    const int jp = tid & 31, pb8 = tid >> 5;     // V: j-pair 2jp, p block pb8*8

    // ldmatrix lane address components
    const int lblk = lid >> 3, lrw = lid & 7;
    const int aRow  = wrow + lrw + (lblk & 1) * 8;        // A frag row
    const int aKoff = (lblk >> 1) * 8;                    // A frag k sub
    const int bRowO = (lblk >> 1) * 8 + lrw;              // B frag row sub
    const int bKoff = (lblk & 1) * 8;                     // B frag k sub

    for (int rr = 0; rr < 2; rr++) {
        const int rt = rr ? (15 - pair) : pair;
        const int row0 = rt * 64;

        // ---------- prologue: Q, Lrow, K(0), VT(0), Ec(0) ----------
        #pragma unroll
        for (int s = 0; s < 4; s++) {
            int row = rbv + 16 * s;
            float4 f = *(const float4*)&q[((b * T_ + row0 + row) * H_ + h) * D_ + 4 * d4];
            uint32_t h0, l0, h1, l1;
            split2(f.x, f.y, h0, l0); split2(f.z, f.w, h1, l1);
            uint32_t off = swz(row * 128 + d4 * 8);
            sts64(sb + QHI_OFF + off, h0, h1);
            sts64(sb + QLO_OFF + off, l0, l1);
        }
        for (int e = tid; e < NLEV_ * 64; e += THREADS) {
            int lev = e >> 6, i = e & 63;
            Lrow[e] = Lsc[(bh * NLEV_ + lev) * T_ + row0 + i] * __expf(cg[row0 + i]);
        }
        #pragma unroll
        for (int s = 0; s < 4; s++) {
            int row = rbv + 16 * s;
            float4 f = *(const float4*)&k[((b * T_ + row) * H_ + h) * D_ + 4 * d4];
            uint32_t h0, l0, h1, l1;
            split2(f.x, f.y, h0, l0); split2(f.z, f.w, h1, l1);
            uint32_t off = swz(row * 128 + d4 * 8);
            sts64(sb + KHI_OFF + off, h0, h1);
            sts64(sb + KLO_OFF + off, l0, l1);
        }
        {
            int j0 = 2 * jp, p0 = pb8 * 8;
            float4 fa  = *(const float4*)&v[((b * T_ + j0)     * H_ + h) * D_ + p0];
            float4 fa2 = *(const float4*)&v[((b * T_ + j0)     * H_ + h) * D_ + p0 + 4];
            float4 fb  = *(const float4*)&v[((b * T_ + j0 + 1) * H_ + h) * D_ + p0];
            float4 fb2 = *(const float4*)&v[((b * T_ + j0 + 1) * H_ + h) * D_ + p0 + 4];
            float aj[8] = {fa.x, fa.y, fa.z, fa.w, fa2.x, fa2.y, fa2.z, fa2.w};
            float bj[8] = {fb.x, fb.y, fb.z, fb.w, fb2.x, fb2.y, fb2.z, fb2.w};
            #pragma unroll
            for (int e = 0; e < 8; e++) {
                uint32_t hi, lo;
                split2(aj[e], bj[e], hi, lo);
                uint32_t off = swz((p0 + e) * 128 + j0 * 2);
                sts32(sb + VT_OFF + off,        hi);
                sts32(sb + VT_OFF + 8192 + off, lo);
            }
        }
        if (tid < 64) EcB[tid] = __expf(-cg[tid]);
        __syncthreads();

        float cO[4][4];
        #pragma unroll
        for (int a = 0; a < 4; a++)
            #pragma unroll
            for (int c = 0; c < 4; c++) cO[a][c] = 0.0f;

        for (int ct = 0; ct <= rt; ct++) {
            const bool pf = (ct < rt);
            const int col0 = ct * 64, col0n = col0 + 64;

            // prefetch K/V(ct+1) into regs
            float4 kf[4], pva, pva2, pvb, pvb2;
            if (pf) {
                #pragma unroll
                for (int s = 0; s < 4; s++)
                    kf[s] = *(const float4*)&k[((b * T_ + col0n + rbv + 16 * s) * H_ + h) * D_ + 4 * d4];
                int j0 = 2 * jp, p0 = pb8 * 8;
                pva  = *(const float4*)&v[((b * T_ + col0n + j0)     * H_ + h) * D_ + p0];
                pva2 = *(const float4*)&v[((b * T_ + col0n + j0)     * H_ + h) * D_ + p0 + 4];
                pvb  = *(const float4*)&v[((b * T_ + col0n + j0 + 1) * H_ + h) * D_ + p0];
                pvb2 = *(const float4*)&v[((b * T_ + col0n + j0 + 1) * H_ + h) * D_ + p0 + 4];
            }

            // ---------------- GEMM1: S = Q K^T ----------------
            float cS[4][4];
            #pragma unroll
            for (int a = 0; a < 4; a++)
                #pragma unroll
                for (int c = 0; c < 4; c++) cS[a][c] = 0.0f;

            #pragma unroll
            for (int ks = 0; ks < 4; ks++) {
                uint32_t aOffA = swz(aRow * 128 + (ks * 16 + aKoff) * 2);
                uint32_t aH0, aH1, aH2, aH3, aL0, aL1, aL2, aL3;
                ldsm4(aH0, aH1, aH2, aH3, sb + QHI_OFF + aOffA);
                ldsm4(aL0, aL1, aL2, aL3, sb + QLO_OFF + aOffA);
                #pragma unroll
                for (int nbp = 0; nbp < 2; nbp++) {
                    uint32_t bOff = swz((wcol + nbp * 16 + bRowO) * 128 +
                                        (ks * 16 + bKoff) * 2);
                    uint32_t bh0, bh1, bh2, bh3, bl0, bl1, bl2, bl3;
                    ldsm4(bh0, bh1, bh2, bh3, sb + KHI_OFF + bOff);
                    ldsm4(bl0, bl1, bl2, bl3, sb + KLO_OFF + bOff);
                    mma16816(cS[2 * nbp],     aH0, aH1, aH2, aH3, bh0, bh1);
                    mma16816(cS[2 * nbp + 1], aH0, aH1, aH2, aH3, bh2, bh3);
                    mma16816(cS[2 * nbp],     aH0, aH1, aH2, aH3, bl0, bl1);
                    mma16816(cS[2 * nbp + 1], aH0, aH1, aH2, aH3, bl2, bl3);
                    mma16816(cS[2 * nbp],     aL0, aL1, aL2, aL3, bh0, bh1);
                    mma16816(cS[2 * nbp + 1], aL0, aL1, aL2, aL3, bh2, bh3);
                }
            }

            // ---------------- weight + split + store S ----------------
            const float* EcCur = EcB + (ct & 1) * 64;
            const int i0 = wrow + gid, i1 = i0 + 8;
            const bool diag = (ct == rt);
            float wi0 = 0.0f, wi1 = 0.0f;
            if (!diag) {
                int lev = 32 - __clz((unsigned)(row0 ^ col0));
                wi0 = Lrow[lev * 64 + i0];
                wi1 = Lrow[lev * 64 + i1];
            }
            #pragma unroll
            for (int nb = 0; nb < 4; nb++) {
                int j0 = wcol + nb * 8 + qcol, j1 = j0 + 1;
                float e0 = EcCur[j0], e1 = EcCur[j1];
                float w00, w01, w10, w11;
                if (diag) {
                    int ig0 = row0 + i0, ig1 = row0 + i1;
                    int jg0 = col0 + j0, jg1 = col0 + j1;
                    auto wgt = [&](int ig, int il, int jg) -> float {
                        if (jg > ig) return 0.0f;
                        unsigned x = (unsigned)(ig ^ jg);
                        int lv = x ? (32 - __clz(x)) : 0;
                        return Lrow[lv * 64 + il];
                    };
                    w00 = wgt(ig0, i0, jg0) * e0; w01 = wgt(ig0, i0, jg1) * e1;
                    w10 = wgt(ig1, i1, jg0) * e0; w11 = wgt(ig1, i1, jg1) * e1;
                } else {
                    w00 = wi0 * e0; w01 = wi0 * e1;
                    w10 = wi1 * e0; w11 = wi1 * e1;
                }
                uint32_t hi, lo;
                uint32_t o0 = swz(i0 * 128 + j0 * 2);
                split2(cS[nb][0] * w00, cS[nb][1] * w01, hi, lo);
                sts32(sb + SHI_OFF + o0, hi);
                sts32(sb + SLO_OFF + o0, lo);
                uint32_t o1 = swz(i1 * 128 + j0 * 2);
                split2(cS[nb][2] * w10, cS[nb][3] * w11, hi, lo);
                sts32(sb + SHI_OFF + o1, hi);
                sts32(sb + SLO_OFF + o1, lo);
            }
            __syncthreads();   // S visible; K/Ec readers done

            // ---------------- write K/V(ct+1), Ec(ct+1) ----------------
            if (pf) {
                #pragma unroll
                for (int s = 0; s < 4; s++) {
                    int row = rbv + 16 * s;
                    uint32_t h0, l0, h1, l1;
                    split2(kf[s].x, kf[s].y, h0, l0);
                    split2(kf[s].z, kf[s].w, h1, l1);
                    uint32_t off = swz(row * 128 + d4 * 8);
                    sts64(sb + KHI_OFF + off, h0, h1);
                    sts64(sb + KLO_OFF + off, l0, l1);
                }
                uint32_t vtb = VT_OFF + ((ct + 1) & 1) * 16384;
                int j0 = 2 * jp, p0 = pb8 * 8;
                float aj[8] = {pva.x, pva.y, pva.z, pva.w, pva2.x, pva2.y, pva2.z, pva2.w};
                float bj[8] = {pvb.x, pvb.y, pvb.z, pvb.w, pvb2.x, pvb2.y, pvb2.z, pvb2.w};
                #pragma unroll
                for (int e = 0; e < 8; e++) {
                    uint32_t hi, lo;
                    split2(aj[e], bj[e], hi, lo);
                    uint32_t off = swz((p0 + e) * 128 + j0 * 2);
                    sts32(sb + vtb + off,        hi);
                    sts32(sb + vtb + 8192 + off, lo);
                }
                if (tid < 64)
                    EcB[((ct + 1) & 1) * 64 + tid] = __expf(-cg[col0n + tid]);
            }

            // ---------------- GEMM2: O += S V ----------------
            uint32_t vcb = VT_OFF + (ct & 1) * 16384;
            #pragma unroll
            for (int ks = 0; ks < 4; ks++) {
                uint32_t aOffA = swz(aRow * 128 + (ks * 16 + aKoff) * 2);
                uint32_t aH0, aH1, aH2, aH3, aL0, aL1, aL2, aL3;
                ldsm4(aH0, aH1, aH2, aH3, sb + SHI_OFF + aOffA);
                ldsm4(aL0, aL1, aL2, aL3, sb + SLO_OFF + aOffA);
                #pragma unroll
                for (int nbp = 0; nbp < 2; nbp++) {
                    uint32_t bOff = swz((wcol + nbp * 16 + bRowO) * 128 +
                                        (ks * 16 + bKoff) * 2);
                    uint32_t bh0, bh1, bh2, bh3, bl0, bl1, bl2, bl3;
                    ldsm4(bh0, bh1, bh2, bh3, sb + vcb + bOff);
                    ldsm4(bl0, bl1, bl2, bl3, sb + vcb + 8192 + bOff);
                    mma16816(cO[2 * nbp],     aH0, aH1, aH2, aH3, bh0, bh1);
                    mma16816(cO[2 * nbp + 1], aH0, aH1, aH2, aH3, bh2, bh3);
                    mma16816(cO[2 * nbp],     aH0, aH1, aH2, aH3, bl0, bl1);
                    mma16816(cO[2 * nbp + 1], aH0, aH1, aH2, aH3, bl2, bl3);
                    mma16816(cO[2 * nbp],     aL0, aL1, aL2, aL3, bh0, bh1);
                    mma16816(cO[2 * nbp + 1], aL0, aL1, aL2, aL3, bh2, bh3);
                }
            }
            __syncthreads();   // S/VT readers done
        }

        // ---------------- store O ----------------
        {
            const int i0 = wrow + gid, i1 = i0 + 8;
            #pragma unroll
            for (int pb = 0; pb < 4; pb++) {
                int p = wcol + pb * 8 + qcol;
                *(float2*)&out[((b * T_ + row0 + i0) * H_ + h) * D_ + p] =
                    make_float2(cO[pb][0], cO[pb][1]);
                *(float2*)&out[((b * T_ + row0 + i1) * H_ + h) * D_ + p] =
                    make_float2(cO[pb][2], cO[pb][3]);
            }
        }
        // next rr's smem writes are safe: final loop sync covers all readers
    }
}

extern "C" void kernel_launch(void* const* d_in, const int* in_sizes, int n_in,
                              void* d_out, int out_size) {
    const float* q   = (const float*)d_in[0];
    const float* k   = (const float*)d_in[1];
    const float* v   = (const float*)d_in[2];
    const float* g   = (const float*)d_in[3];
    const float* Lsc = (const float*)d_in[4];
    float* out = (float*)d_out;

    cudaFuncSetAttribute(hattn_mma, cudaFuncAttributeMaxDynamicSharedMemorySize,
                         SMEM_TOTAL);
    scan_kernel<<<BHN, T_>>>(g);
    hattn_mma<<<128, THREADS, SMEM_TOTAL>>>(q, k, v, Lsc, out);
}

// round 15
// speedup vs baseline: 1.7661x; 1.0369x over previous
#include <cuda_runtime.h>
#include <cuda_bf16.h>
#include <cstdint>

#define B_    2
#define T_    1024
#define H_    8
#define BHN   16
#define NLEV_ 11
#define D_    64
#define THREADS 256

// smem layout; every tile has 128B rows (64 bf16), SW128 swizzle
#define Q_OFF     0          // hi +0, lo +8192 (16K)
#define K_OFF     16384      // 2 bufs x 16K (hi +0, lo +8192)
#define V_OFF     49152      // 3 bufs x 16K
#define S_OFF     98304      // 2 bufs x 16K
#define LROW_OFF  131072     // float[11][64]
#define EC_OFF    133888     // float[2][64]
#define SMEM_TOTAL 134400

static __device__ float d_cumg[BHN * T_];

__device__ __forceinline__ uint32_t smem_u32(const void* p) {
    uint32_t a;
    asm("{ .reg .u64 t; cvta.to.shared.u64 t, %1; cvt.u32.u64 %0, t; }"
        : "=r"(a) : "l"(p));
    return a;
}
__device__ __forceinline__ uint32_t swz(uint32_t o) { return o ^ ((o >> 3) & 0x70); }

__device__ __forceinline__ void ldsm4(uint32_t& r0, uint32_t& r1, uint32_t& r2,
                                      uint32_t& r3, uint32_t a) {
    asm volatile("ldmatrix.sync.aligned.m8n8.x4.shared.b16 {%0,%1,%2,%3}, [%4];"
                 : "=r"(r0), "=r"(r1), "=r"(r2), "=r"(r3) : "r"(a));
}
__device__ __forceinline__ void mma16816(float* c, uint32_t a0, uint32_t a1,
                                         uint32_t a2, uint32_t a3,
                                         uint32_t b0, uint32_t b1) {
    asm volatile(
        "mma.sync.aligned.m16n8k16.row.col.f32.bf16.bf16.f32 "
        "{%0,%1,%2,%3}, {%4,%5,%6,%7}, {%8,%9}, {%0,%1,%2,%3};"
        : "+f"(c[0]), "+f"(c[1]), "+f"(c[2]), "+f"(c[3])
        : "r"(a0), "r"(a1), "r"(a2), "r"(a3), "r"(b0), "r"(b1));
}
__device__ __forceinline__ void sts64(uint32_t a, uint32_t r0, uint32_t r1) {
    asm volatile("st.shared.v2.b32 [%0], {%1,%2};" :: "r"(a), "r"(r0), "r"(r1) : "memory");
}
__device__ __forceinline__ void sts32(uint32_t a, uint32_t r0) {
    asm volatile("st.shared.b32 [%0], %1;" :: "r"(a), "r"(r0) : "memory");
}
// split (x0,x1) -> packed bf16x2 hi and lo residual
__device__ __forceinline__ void split2(float x0, float x1, uint32_t& hi, uint32_t& lo) {
    __nv_bfloat16 h0 = __float2bfloat16(x0), h1 = __float2bfloat16(x1);
    hi = ((uint32_t)__bfloat16_as_ushort(h1) << 16) | __bfloat16_as_ushort(h0);
    float l0 = x0 - __bfloat162float(h0);
    float l1 = x1 - __bfloat162float(h1);
    __nv_bfloat16 g0 = __float2bfloat16(l0), g1 = __float2bfloat16(l1);
    lo = ((uint32_t)__bfloat16_as_ushort(g1) << 16) | __bfloat16_as_ushort(g0);
}

__global__ void __launch_bounds__(1024) scan_kernel(const float* __restrict__ g) {
    __shared__ float s[T_];
    int bh = blockIdx.x;
    int b = bh >> 3, h = bh & 7;
    int t = threadIdx.x;
    s[t] = g[(b * T_ + t) * H_ + h];
    __syncthreads();
    #pragma unroll
    for (int off = 1; off < T_; off <<= 1) {
        float add = (t >= off) ? s[t - off] : 0.0f;
        __syncthreads();
        s[t] += add;
        __syncthreads();
    }
    d_cumg[bh * T_ + t] = s[t];
}

// grid = 128 = 16 (b,h) x 8 balanced row-tile pairs {p, 15-p} (64 rows each).
// W[i,j] = [j<=i]*exp(cumg_i)*L[lev(i,j),i]*exp(-cumg_j); lev = 32-clz(i^j).
// exp(-cumg_j) is folded into the bf16-split K tiles; exp(cumg_i) into Lrow.
// Single barrier per col tile: K/S double-buffered, V triple-buffered, so
// GEMM2(ct) and GEMM1(ct+1) share one region and interleave.
__global__ void __launch_bounds__(THREADS) hattn_mma(
    const float* __restrict__ q, const float* __restrict__ k,
    const float* __restrict__ v, const float* __restrict__ Lsc,
    float* __restrict__ out)
{
    extern __shared__ char smem[];
    const uint32_t sb = smem_u32(smem);
    const int tid = threadIdx.x;
    const int lid = tid & 31, wid = tid >> 5;
    const int gid = lid >> 2, qcol = 2 * (lid & 3);
    const int wrow = (wid & 3) * 16, wcol = (wid >> 2) * 32;
    const int blk = blockIdx.x;
    const int bh = blk & 15, pair = blk >> 4;
    const int b = bh >> 3, h = bh & 7;

    float* Lrow = (float*)(smem + LROW_OFF);
    float* EcB  = (float*)(smem + EC_OFF);
    const float* cg = d_cumg + bh * T_;

    // load-mapping lanes
    const int d4 = tid & 15, rbv = tid >> 4;     // Q/K: float4 over d
    const int jp = tid & 31, pb8 = tid >> 5;     // V: j-pair 2jp, p block pb8*8

    // ldmatrix lane address components
    const int lblk = lid >> 3, lrw = lid & 7;
    const int aRow  = wrow + lrw + (lblk & 1) * 8;
    const int aKoff = (lblk >> 1) * 8;
    const int bRowO = (lblk >> 1) * 8 + lrw;
    const int bKoff = (lblk & 1) * 8;

    for (int rr = 0; rr < 2; rr++) {
        const int rt = rr ? (15 - pair) : pair;
        const int row0 = rt * 64;

        // ---------- prologue A: Q smem, Lrow, Ec slots 0/1 ----------
        #pragma unroll
        for (int s = 0; s < 4; s++) {
            int row = rbv + 16 * s;
            float4 f = *(const float4*)&q[((b * T_ + row0 + row) * H_ + h) * D_ + 4 * d4];
            uint32_t h0, l0, h1, l1;
            split2(f.x, f.y, h0, l0); split2(f.z, f.w, h1, l1);
            uint32_t off = swz(row * 128 + d4 * 8);
            sts64(sb + Q_OFF + off, h0, h1);
            sts64(sb + Q_OFF + 8192 + off, l0, l1);
        }
        for (int e = tid; e < NLEV_ * 64; e += THREADS) {
            int lev = e >> 6, i = e & 63;
            Lrow[e] = Lsc[(bh * NLEV_ + lev) * T_ + row0 + i] * __expf(cg[row0 + i]);
        }
        if (tid < 128) EcB[tid] = __expf(-cg[tid]);  // slot0 = Ec(tile0), slot1 = Ec(tile1)
        __syncthreads();

        // ---------- prologue B: K(0) (Ec-folded), V(0), Q frag hoist ----------
        #pragma unroll
        for (int s = 0; s < 4; s++) {
            int row = rbv + 16 * s;
            float ec = EcB[row];
            float4 f = *(const float4*)&k[((b * T_ + row) * H_ + h) * D_ + 4 * d4];
            uint32_t h0, l0, h1, l1;
            split2(f.x * ec, f.y * ec, h0, l0);
            split2(f.z * ec, f.w * ec, h1, l1);
            uint32_t off = swz(row * 128 + d4 * 8);
            sts64(sb + K_OFF + off, h0, h1);
            sts64(sb + K_OFF + 8192 + off, l0, l1);
        }
        {
            int j0 = 2 * jp, p0 = pb8 * 8;
            float4 fa  = *(const float4*)&v[((b * T_ + j0)     * H_ + h) * D_ + p0];
            float4 fa2 = *(const float4*)&v[((b * T_ + j0)     * H_ + h) * D_ + p0 + 4];
            float4 fb  = *(const float4*)&v[((b * T_ + j0 + 1) * H_ + h) * D_ + p0];
            float4 fb2 = *(const float4*)&v[((b * T_ + j0 + 1) * H_ + h) * D_ + p0 + 4];
            float aj[8] = {fa.x, fa.y, fa.z, fa.w, fa2.x, fa2.y, fa2.z, fa2.w};
            float bj[8] = {fb.x, fb.y, fb.z, fb.w, fb2.x, fb2.y, fb2.z, fb2.w};
            #pragma unroll
            for (int e = 0; e < 8; e++) {
                uint32_t hi, lo;
                split2(aj[e], bj[e], hi, lo);
                uint32_t off = swz((p0 + e) * 128 + j0 * 2);
                sts32(sb + V_OFF + off,        hi);
                sts32(sb + V_OFF + 8192 + off, lo);
            }
        }
        // hoist Q fragments (A operand of GEMM1, constant over ct loop)
        uint32_t qh[4][4], ql[4][4];
        #pragma unroll
        for (int ks = 0; ks < 4; ks++) {
            uint32_t aOffA = swz(aRow * 128 + (ks * 16 + aKoff) * 2);
            ldsm4(qh[ks][0], qh[ks][1], qh[ks][2], qh[ks][3], sb + Q_OFF + aOffA);
            ldsm4(ql[ks][0], ql[ks][1], ql[ks][2], ql[ks][3], sb + Q_OFF + 8192 + aOffA);
        }
        __syncthreads();

        float cO[4][4];
        #pragma unroll
        for (int a = 0; a < 4; a++)
            #pragma unroll
            for (int c = 0; c < 4; c++) cO[a][c] = 0.0f;

        for (int ct = 0; ct <= rt; ct++) {
            const bool pf = (ct < rt);
            const int col0 = ct * 64, col0n = col0 + 64;

            // prefetch K/V(ct+1) into regs
            float4 kf[4], pva, pva2, pvb, pvb2;
            if (pf) {
                #pragma unroll
                for (int s = 0; s < 4; s++)
                    kf[s] = *(const float4*)&k[((b * T_ + col0n + rbv + 16 * s) * H_ + h) * D_ + 4 * d4];
                int j0 = 2 * jp, p0 = pb8 * 8;
                pva  = *(const float4*)&v[((b * T_ + col0n + j0)     * H_ + h) * D_ + p0];
                pva2 = *(const float4*)&v[((b * T_ + col0n + j0)     * H_ + h) * D_ + p0 + 4];
                pvb  = *(const float4*)&v[((b * T_ + col0n + j0 + 1) * H_ + h) * D_ + p0];
                pvb2 = *(const float4*)&v[((b * T_ + col0n + j0 + 1) * H_ + h) * D_ + p0 + 4];
            }
            // Ec(ct+2) -> slot ct&1 (read next iter; visibility via this iter's sync)
            if (tid < 64 && ct + 2 <= rt)
                EcB[(ct & 1) * 64 + tid] = __expf(-cg[(ct + 2) * 64 + tid]);

            // ---------------- GEMM1: S = Q K^T (K Ec-folded) ----------------
            float cS[4][4];
            #pragma unroll
            for (int a = 0; a < 4; a++)
                #pragma unroll
                for (int c = 0; c < 4; c++) cS[a][c] = 0.0f;

            const uint32_t kb = sb + K_OFF + (ct & 1) * 16384;
            #pragma unroll
            for (int ks = 0; ks < 4; ks++) {
                #pragma unroll
                for (int nbp = 0; nbp < 2; nbp++) {
                    uint32_t bOff = swz((wcol + nbp * 16 + bRowO) * 128 +
                                        (ks * 16 + bKoff) * 2);
                    uint32_t bh0, bh1, bh2, bh3, bl0, bl1, bl2, bl3;
                    ldsm4(bh0, bh1, bh2, bh3, kb + bOff);
                    ldsm4(bl0, bl1, bl2, bl3, kb + 8192 + bOff);
                    mma16816(cS[2 * nbp],     qh[ks][0], qh[ks][1], qh[ks][2], qh[ks][3], bh0, bh1);
                    mma16816(cS[2 * nbp + 1], qh[ks][0], qh[ks][1], qh[ks][2], qh[ks][3], bh2, bh3);
                    mma16816(cS[2 * nbp],     qh[ks][0], qh[ks][1], qh[ks][2], qh[ks][3], bl0, bl1);
                    mma16816(cS[2 * nbp + 1], qh[ks][0], qh[ks][1], qh[ks][2], qh[ks][3], bl2, bl3);
                    mma16816(cS[2 * nbp],     ql[ks][0], ql[ks][1], ql[ks][2], ql[ks][3], bh0, bh1);
                    mma16816(cS[2 * nbp + 1], ql[ks][0], ql[ks][1], ql[ks][2], ql[ks][3], bh2, bh3);
                }
            }

            // ---------------- weight (Lrow only) + split + store S[ct&1] ----------------
            const uint32_t sbase = sb + S_OFF + (ct & 1) * 16384;
            const int i0 = wrow + gid, i1 = i0 + 8;
            const bool diag = (ct == rt);
            float wi0 = 0.0f, wi1 = 0.0f;
            if (!diag) {
                int lev = 32 - __clz((unsigned)(row0 ^ col0));
                wi0 = Lrow[lev * 64 + i0];
                wi1 = Lrow[lev * 64 + i1];
            }
            #pragma unroll
            for (int nb = 0; nb < 4; nb++) {
                int j0 = wcol + nb * 8 + qcol, j1 = j0 + 1;
                float w00, w01, w10, w11;
                if (diag) {
                    int ig0 = row0 + i0, ig1 = row0 + i1;
                    int jg0 = col0 + j0, jg1 = col0 + j1;
                    auto wgt = [&](int ig, int il, int jg) -> float {
                        if (jg > ig) return 0.0f;
                        unsigned x = (unsigned)(ig ^ jg);
                        int lv = x ? (32 - __clz(x)) : 0;
                        return Lrow[lv * 64 + il];
                    };
                    w00 = wgt(ig0, i0, jg0); w01 = wgt(ig0, i0, jg1);
                    w10 = wgt(ig1, i1, jg0); w11 = wgt(ig1, i1, jg1);
                } else {
                    w00 = wi0; w01 = wi0;
                    w10 = wi1; w11 = wi1;
                }
                uint32_t hi, lo;
                uint32_t o0 = swz(i0 * 128 + j0 * 2);
                split2(cS[nb][0] * w00, cS[nb][1] * w01, hi, lo);
                sts32(sbase + o0, hi);
                sts32(sbase + 8192 + o0, lo);
                uint32_t o1 = swz(i1 * 128 + j0 * 2);
                split2(cS[nb][2] * w10, cS[nb][3] * w11, hi, lo);
                sts32(sbase + o1, hi);
                sts32(sbase + 8192 + o1, lo);
            }

            // ---------------- writeback K[(ct+1)&1] (Ec-folded), V[(ct+1)%3] ----------------
            if (pf) {
                const uint32_t kbn = sb + K_OFF + ((ct + 1) & 1) * 16384;
                #pragma unroll
                for (int s = 0; s < 4; s++) {
                    int row = rbv + 16 * s;
                    float ec = EcB[((ct + 1) & 1) * 64 + row];
                    uint32_t h0, l0, h1, l1;
                    split2(kf[s].x * ec, kf[s].y * ec, h0, l0);
                    split2(kf[s].z * ec, kf[s].w * ec, h1, l1);
                    uint32_t off = swz(row * 128 + d4 * 8);
                    sts64(kbn + off, h0, h1);
                    sts64(kbn + 8192 + off, l0, l1);
                }
                const uint32_t vtb = sb + V_OFF + ((ct + 1) % 3) * 16384;
                int j0 = 2 * jp, p0 = pb8 * 8;
                float aj[8] = {pva.x, pva.y, pva.z, pva.w, pva2.x, pva2.y, pva2.z, pva2.w};
                float bj[8] = {pvb.x, pvb.y, pvb.z, pvb.w, pvb2.x, pvb2.y, pvb2.z, pvb2.w};
                #pragma unroll
                for (int e = 0; e < 8; e++) {
                    uint32_t hi, lo;
                    split2(aj[e], bj[e], hi, lo);
                    uint32_t off = swz((p0 + e) * 128 + j0 * 2);
                    sts32(vtb + off,        hi);
                    sts32(vtb + 8192 + off, lo);
                }
            }
            __syncthreads();   // single barrier: S[ct], K/V(ct+1) visible

            // ---------------- GEMM2: O += S V (interleaves with next GEMM1) ----------------
            const uint32_t vcb = sb + V_OFF + (ct % 3) * 16384;
            #pragma unroll
            for (int ks = 0; ks < 4; ks++) {
                uint32_t aOffA = swz(aRow * 128 + (ks * 16 + aKoff) * 2);
                uint32_t aH0, aH1, aH2, aH3, aL0, aL1, aL2, aL3;
                ldsm4(aH0, aH1, aH2, aH3, sbase + aOffA);
                ldsm4(aL0, aL1, aL2, aL3, sbase + 8192 + aOffA);
                #pragma unroll
                for (int nbp = 0; nbp < 2; nbp++) {
                    uint32_t bOff = swz((wcol + nbp * 16 + bRowO) * 128 +
                                        (ks * 16 + bKoff) * 2);
                    uint32_t bh0, bh1, bh2, bh3, bl0, bl1, bl2, bl3;
                    ldsm4(bh0, bh1, bh2, bh3, vcb + bOff);
                    ldsm4(bl0, bl1, bl2, bl3, vcb + 8192 + bOff);
                    mma16816(cO[2 * nbp],     aH0, aH1, aH2, aH3, bh0, bh1);
                    mma16816(cO[2 * nbp + 1], aH0, aH1, aH2, aH3, bh2, bh3);
                    mma16816(cO[2 * nbp],     aH0, aH1, aH2, aH3, bl0, bl1);
                    mma16816(cO[2 * nbp + 1], aH0, aH1, aH2, aH3, bl2, bl3);
                    mma16816(cO[2 * nbp],     aL0, aL1, aL2, aL3, bh0, bh1);
                    mma16816(cO[2 * nbp + 1], aL0, aL1, aL2, aL3, bh2, bh3);
                }
            }
        }

        // ---------------- store O ----------------
        {
            const int i0 = wrow + gid, i1 = i0 + 8;
            #pragma unroll
            for (int pb = 0; pb < 4; pb++) {
                int p = wcol + pb * 8 + qcol;
                *(float2*)&out[((b * T_ + row0 + i0) * H_ + h) * D_ + p] =
                    make_float2(cO[pb][0], cO[pb][1]);
                *(float2*)&out[((b * T_ + row0 + i1) * H_ + h) * D_ + p] =
                    make_float2(cO[pb][2], cO[pb][3]);
            }
        }
        // next rr prologue-A writes (Q/Lrow/Ec) don't conflict with GEMM2(rt)
        // readers (S/V); prologue-B's V-buf0 write is fenced by prologue sync.
    }
}

extern "C" void kernel_launch(void* const* d_in, const int* in_sizes, int n_in,
                              void* d_out, int out_size) {
    const float* q   = (const float*)d_in[0];
    const float* k   = (const float*)d_in[1];
    const float* v   = (const float*)d_in[2];
    const float* g   = (const float*)d_in[3];
    const float* Lsc = (const float*)d_in[4];
    float* out = (float*)d_out;

    cudaFuncSetAttribute(hattn_mma, cudaFuncAttributeMaxDynamicSharedMemorySize,
                         SMEM_TOTAL);
    scan_kernel<<<BHN, T_>>>(g);
    hattn_mma<<<128, THREADS, SMEM_TOTAL>>>(q, k, v, Lsc, out);
}